// round 7
// baseline (speedup 1.0000x reference)
#include <cuda_runtime.h>
#include <mma.h>
#include <cstdint>
#include <cstddef>

using namespace nvcuda;

// ============================================================================
// Problem: hidden [B,2048] f32, labels [B,28] i64/i32, W [280,2048] f32,
// bias [280] f32.  logits = hidden @ W^T + bias;  loss = mean NLL / 28.
// ============================================================================
static constexpr int KDIM = 2048;
static constexpr int NTOT = 280;
static constexpr int NPAD = 288;       // 18 * 16
static constexpr int BM   = 128;
static constexpr int BK   = 32;
static constexpr int NCH  = KDIM / BK; // 64
static constexpr int THREADS = 384;    // 12 warps: 2 (m) x 6 (n)
static constexpr int STAGES = 3;

static constexpr int LDA = 36;
static constexpr int LDB = 36;
static constexpr int LDC = 292;

// SMEM layout (bytes)
static constexpr int SM_BIAS  = 0;                       // 288 f32
static constexpr int SM_STG   = 1280;
static constexpr int A_SZ     = BM * LDA * 4;            // 18432
static constexpr int B_SZ     = NPAD * LDB * 4;          // 41472
static constexpr int STAGE_SZ = A_SZ + B_SZ;             // 59904
static constexpr int SM_TOTAL = SM_STG + STAGES * STAGE_SZ;  // 180992
static constexpr int SM_C     = SM_STG;                  // full C: 128*292*4 = 149504 fits

// RN tf32 (W prep only; A relies on HW truncation inside the MMA)
__device__ __forceinline__ float to_tf32(float x) {
    uint32_t y;
    asm("cvt.rna.tf32.f32 %0, %1;" : "=r"(y) : "f"(x));
    return __uint_as_float(y);
}

__device__ __forceinline__ uint32_t smem_u32(const void* p) {
    uint32_t a;
    asm("{ .reg .u64 t; cvta.to.shared.u64 t, %1; cvt.u32.u64 %0, t; }"
        : "=r"(a) : "l"(p));
    return a;
}

#define CP_ASYNC16(dst, src) \
    asm volatile("cp.async.cg.shared.global [%0], [%1], 16;" \
                 :: "r"(dst), "l"(src))
#define CP_COMMIT() asm volatile("cp.async.commit_group;" ::: "memory")
#define CP_WAIT(n)  asm volatile("cp.async.wait_group %0;" :: "n"(n) : "memory")

// ============================================================================
// Device scratch
// ============================================================================
__device__ float g_wpad[NPAD * KDIM];     // tf32-rounded, zero-padded W
__device__ float g_logits_scratch[32768 * NTOT];
__device__ float g_loss_scratch[1];
__device__ int   g_lab64;

// ============================================================================
// Prep: W -> g_wpad (RN tf32, rows >= 280 zero). Label dtype detect.
// ============================================================================
__global__ void prep_kernel(const float* __restrict__ W,
                            const int* __restrict__ lab) {
    int idx = blockIdx.x * blockDim.x + threadIdx.x;
    if (idx < NPAD * KDIM) {
        int r = idx >> 11;   // / 2048
        g_wpad[idx] = (r < NTOT) ? to_tf32(W[idx]) : 0.f;
    }
    if (idx == 0) {
        int odd_or = 0;
        #pragma unroll 8
        for (int i = 0; i < 64; i++) odd_or |= lab[2 * i + 1];
        g_lab64 = (odd_or == 0) ? 1 : 0;
    }
}

// ============================================================================
// Fused GEMM (tf32 wmma, cp.async 3-stage pipeline) + bias + logits + loss
// ============================================================================
__global__ void __launch_bounds__(THREADS, 1)
gemm_loss_kernel(const float* __restrict__ hidden,
                 const float* __restrict__ bias,
                 const int*   __restrict__ lab,
                 float* __restrict__ logits_arg,
                 float* __restrict__ loss_out,
                 int batch)
{
    extern __shared__ char smem[];
    float* sbias = reinterpret_cast<float*>(smem + SM_BIAS);
    float* logits = logits_arg ? logits_arg : g_logits_scratch;

    const uint32_t sbase = smem_u32(smem);
    const int tid = threadIdx.x;
    const int wid = tid >> 5;
    const int wm  = wid / 6;     // 0..1 -> 64-row slice
    const int wn  = wid % 6;     // 0..5 -> 48-col slice
    const int m0  = blockIdx.x * BM;

    for (int i = tid; i < NPAD; i += THREADS)
        sbias[i] = (i < NTOT) ? bias[i] : 0.f;

    wmma::fragment<wmma::accumulator, 16, 16, 8, float> c[4][3];
    #pragma unroll
    for (int i = 0; i < 4; i++)
        #pragma unroll
        for (int j = 0; j < 3; j++)
            wmma::fill_fragment(c[i][j], 0.f);

    // ---- cp.async stage issue: A 128x32 raw f32, B 288x32 pre-rounded ----
    auto issue_stage = [&](int kc, int buf) {
        const uint32_t a_dst = sbase + SM_STG + buf * STAGE_SZ;
        const uint32_t b_dst = a_dst + A_SZ;
        const int k0 = kc * BK;
        // A: 1024 x 16B
        #pragma unroll
        for (int i = 0; i < 3; i++) {
            int idx = tid + i * THREADS;
            if (idx < 1024) {
                int r = idx >> 3, v = idx & 7;
                const float* src = hidden + (size_t)(m0 + r) * KDIM + k0 + v * 4;
                CP_ASYNC16(a_dst + (uint32_t)(r * LDA + v * 4) * 4, src);
            }
        }
        // B: 2304 x 16B (6 per thread exact)
        #pragma unroll
        for (int i = 0; i < 6; i++) {
            int idx = tid + i * THREADS;
            int r = idx >> 3, v = idx & 7;
            const float* src = g_wpad + (size_t)r * KDIM + k0 + v * 4;
            CP_ASYNC16(b_dst + (uint32_t)(r * LDB + v * 4) * 4, src);
        }
    };

    issue_stage(0, 0); CP_COMMIT();
    issue_stage(1, 1); CP_COMMIT();

    for (int kc = 0; kc < NCH; kc++) {
        CP_WAIT(1);            // stage kc complete (kc+1 may be in flight)
        __syncthreads();

        // Prefetch FIRST: LDGSTS issue + memory latency hide under this
        // chunk's MMAs. Hazard-safe: (kc+2)%3 was drained before the barrier.
        if (kc + 2 < NCH) issue_stage(kc + 2, (kc + 2) % STAGES);
        CP_COMMIT();           // uniform group count even when empty

        const int buf = kc % STAGES;
        const float* As = reinterpret_cast<const float*>(
            smem + SM_STG + buf * STAGE_SZ);
        const float* Bs = As + A_SZ / 4;

        #pragma unroll
        for (int ks = 0; ks < 4; ks++) {
            const int k0 = ks * 8;
            wmma::fragment<wmma::matrix_a, 16, 16, 8, wmma::precision::tf32,
                           wmma::row_major> a[4];
            wmma::fragment<wmma::matrix_b, 16, 16, 8, wmma::precision::tf32,
                           wmma::col_major> b[3];
            #pragma unroll
            for (int i = 0; i < 4; i++)
                wmma::load_matrix_sync(a[i], As + (wm * 64 + i * 16) * LDA + k0, LDA);
            #pragma unroll
            for (int j = 0; j < 3; j++)
                wmma::load_matrix_sync(b[j], Bs + (wn * 48 + j * 16) * LDB + k0, LDB);
            #pragma unroll
            for (int i = 0; i < 4; i++)
                #pragma unroll
                for (int j = 0; j < 3; j++)
                    wmma::mma_sync(c[i][j], a[i], b[j], c[i][j]);
        }
    }
    __syncthreads();           // all warps done with stage smem

    // ---- epilogue: full 128x292 C in smem (one pass) ----
    float* Cs = reinterpret_cast<float*>(smem + SM_C);
    #pragma unroll
    for (int i = 0; i < 4; i++)
        #pragma unroll
        for (int j = 0; j < 3; j++)
            wmma::store_matrix_sync(
                Cs + (wm * 64 + i * 16) * LDC + wn * 48 + j * 16,
                c[i][j], LDC, wmma::mem_row_major);
    __syncthreads();

    // logits write-out: float4 LDS (aligned) -> 4 scalar STG (logits base may
    // be only 4B-aligned when output layout is [loss, logits...]).
    for (int idx = tid; idx < BM * (NTOT / 4); idx += THREADS) {
        int r = idx / (NTOT / 4), n4 = idx - r * (NTOT / 4);
        float4 v  = *reinterpret_cast<const float4*>(Cs + r * LDC + n4 * 4);
        float4 bb = *reinterpret_cast<const float4*>(sbias + n4 * 4);
        float* dst = logits + (size_t)(m0 + r) * NTOT + n4 * 4;
        dst[0] = v.x + bb.x;
        dst[1] = v.y + bb.y;
        dst[2] = v.z + bb.z;
        dst[3] = v.w + bb.w;
    }

    // loss: 128 rows x 28 heads
    const int lab64 = g_lab64;
    float loss_part = 0.f;
    for (int t = tid; t < BM * 28; t += THREADS) {
        int r = t / 28, h = t - r * 28;
        const float* x  = Cs + r * LDC + h * 10;
        const float* bb = sbias + h * 10;
        float v[10], mx = -1e30f;
        #pragma unroll
        for (int i = 0; i < 10; i++) { v[i] = x[i] + bb[i]; mx = fmaxf(mx, v[i]); }
        float s = 0.f;
        #pragma unroll
        for (int i = 0; i < 10; i++) s += __expf(v[i] - mx);
        int li = (m0 + r) * 28 + h;
        int label = lab64 ? lab[2 * li] : lab[li];
        loss_part += mx + __logf(s) - v[label];
    }

    #pragma unroll
    for (int off = 16; off > 0; off >>= 1)
        loss_part += __shfl_xor_sync(0xFFFFFFFF, loss_part, off);
    __shared__ float warp_loss[12];
    if ((tid & 31) == 0) warp_loss[wid] = loss_part;
    __syncthreads();
    if (tid == 0) {
        float t = 0.f;
        #pragma unroll
        for (int i = 0; i < 12; i++) t += warp_loss[i];
        atomicAdd(loss_out, t * (1.0f / ((float)batch * 28.0f)));
    }
}

// ============================================================================
// kernel_launch
// ============================================================================
extern "C" void kernel_launch(void* const* d_in, const int* in_sizes, int n_in,
                              void* d_out, int out_size)
{
    const float* hidden = (const float*)d_in[0];
    const int*   labels = (const int*)d_in[1];
    const float* W      = (const float*)d_in[2];
    const float* bias   = (const float*)d_in[3];

    const int batch = in_sizes[0] / KDIM;                  // 32768
    const long long LOGN = (long long)batch * NTOT;

    float* out = (float*)d_out;
    float* loss_ptr = nullptr;
    float* logits_ptr = nullptr;
    if ((long long)out_size >= LOGN + 1) {
        loss_ptr = out;
        logits_ptr = out + 1;
    } else if ((long long)out_size == LOGN) {
        logits_ptr = out;
    } else {
        loss_ptr = out;
    }
    if (!loss_ptr) {
        void* p = nullptr;
        cudaGetSymbolAddress(&p, g_loss_scratch);
        loss_ptr = (float*)p;
    }

    static bool attr_done = false;
    if (!attr_done) {
        cudaFuncSetAttribute(gemm_loss_kernel,
                             cudaFuncAttributeMaxDynamicSharedMemorySize, SM_TOTAL);
        attr_done = true;
    }

    prep_kernel<<<(NPAD * KDIM + 255) / 256, 256>>>(W, labels);
    cudaMemsetAsync(loss_ptr, 0, sizeof(float));
    gemm_loss_kernel<<<batch / BM, THREADS, SM_TOTAL>>>(
        hidden, bias, labels, logits_ptr, loss_ptr, batch);
}

// round 9
// speedup vs baseline: 3.1256x; 3.1256x over previous
#include <cuda_runtime.h>
#include <cuda_fp16.h>
#include <mma.h>
#include <cstdint>
#include <cstddef>

using namespace nvcuda;

// ============================================================================
// Problem: hidden [B,2048] f32, labels [B,28] i64/i32, W [280,2048] f32,
// bias [280] f32.  logits = hidden @ W^T + bias;  loss = mean NLL / 28.
// fp16 HMMA lane: A converted f32->fp16 in-kernel, W pre-converted once.
// ============================================================================
static constexpr int KDIM = 2048;
static constexpr int NTOT = 280;
static constexpr int NPAD = 288;        // 18 * 16
static constexpr int BM   = 128;
static constexpr int BK   = 32;         // K per chunk
static constexpr int NCH  = KDIM / BK;  // 64
static constexpr int THREADS = 384;     // 12 warps: 2 (m) x 6 (n)
static constexpr int STAGES = 3;

static constexpr int LDA_RAW = 36;      // raw A row: 32 f32 + 4 pad (144B)
static constexpr int LDH     = 40;      // fp16 rows: 32 halves + 8 pad (80B)
static constexpr int LDC     = 292;     // f32 C rows

// SMEM layout (bytes)
static constexpr int SM_BIAS   = 0;                          // 288 f32
static constexpr int SM_STG    = 1280;
static constexpr int A_RAW_SZ  = BM * LDA_RAW * 4;           // 18432
static constexpr int B_SZ      = NPAD * LDH * 2;             // 23040
static constexpr int STAGE_SZ  = A_RAW_SZ + B_SZ;            // 41472
static constexpr int SM_AH     = SM_STG + STAGES * STAGE_SZ; // 125696
static constexpr int AH_SZ     = BM * LDH * 2;               // 10240
static constexpr int SM_C      = SM_STG;                     // epilogue reuse
static constexpr int SM_EPI    = SM_STG + BM * LDC * 4;      // 150784
static constexpr int SM_TOTAL  = (SM_AH + AH_SZ > SM_EPI) ? (SM_AH + AH_SZ) : SM_EPI;

__device__ __forceinline__ uint32_t smem_u32(const void* p) {
    uint32_t a;
    asm("{ .reg .u64 t; cvta.to.shared.u64 t, %1; cvt.u32.u64 %0, t; }"
        : "=r"(a) : "l"(p));
    return a;
}

#define CP_ASYNC16(dst, src) \
    asm volatile("cp.async.cg.shared.global [%0], [%1], 16;" \
                 :: "r"(dst), "l"(src))
#define CP_COMMIT() asm volatile("cp.async.commit_group;" ::: "memory")
#define CP_WAIT(n)  asm volatile("cp.async.wait_group %0;" :: "n"(n) : "memory")

// ============================================================================
// Device scratch
// ============================================================================
__device__ __half g_whalf[NPAD * KDIM];   // fp16 RN, zero-padded W
__device__ float  g_logits_scratch[32768 * NTOT];
__device__ float  g_loss_scratch[1];
__device__ int    g_lab64;

// ============================================================================
// Prep: W -> g_whalf (fp16 RN, rows >= 280 zero). Label dtype detect.
// ============================================================================
__global__ void prep_kernel(const float* __restrict__ W,
                            const int* __restrict__ lab) {
    int idx = blockIdx.x * blockDim.x + threadIdx.x;
    if (idx < NPAD * KDIM) {
        int r = idx >> 11;   // / 2048
        g_whalf[idx] = (r < NTOT) ? __float2half_rn(W[idx]) : __half(0.f);
    }
    if (idx == 0) {
        int odd_or = 0;
        #pragma unroll 8
        for (int i = 0; i < 64; i++) odd_or |= lab[2 * i + 1];
        g_lab64 = (odd_or == 0) ? 1 : 0;
    }
}

// ============================================================================
// Fused GEMM (fp16 wmma m16n16k16, 3-stage cp.async) + bias + logits + loss
// ============================================================================
__global__ void __launch_bounds__(THREADS, 1)
gemm_loss_kernel(const float* __restrict__ hidden,
                 const float* __restrict__ bias,
                 const int*   __restrict__ lab,
                 float* __restrict__ logits_arg,
                 float* __restrict__ loss_out,
                 int batch)
{
    extern __shared__ char smem[];
    float* sbias = reinterpret_cast<float*>(smem + SM_BIAS);
    float* logits = logits_arg ? logits_arg : g_logits_scratch;

    const uint32_t sbase = smem_u32(smem);
    const int tid = threadIdx.x;
    const int wid = tid >> 5;
    const int wm  = wid / 6;     // 0..1 -> 64-row slice
    const int wn  = wid % 6;     // 0..5 -> 48-col slice
    const int m0  = blockIdx.x * BM;

    for (int i = tid; i < NPAD; i += THREADS)
        sbias[i] = (i < NTOT) ? bias[i] : 0.f;

    wmma::fragment<wmma::accumulator, 16, 16, 16, float> c[4][3];
    #pragma unroll
    for (int i = 0; i < 4; i++)
        #pragma unroll
        for (int j = 0; j < 3; j++)
            wmma::fill_fragment(c[i][j], 0.f);

    // ---- cp.async stage: raw f32 A 128x32 (+pad), fp16 B 288x32 (+pad) ----
    auto issue_stage = [&](int kc, int buf) {
        const uint32_t a_dst = sbase + SM_STG + buf * STAGE_SZ;
        const uint32_t b_dst = a_dst + A_RAW_SZ;
        const int k0 = kc * BK;
        // A raw: 1024 x 16B (8 per row)
        #pragma unroll
        for (int i = 0; i < 3; i++) {
            int idx = tid + i * THREADS;
            if (idx < 1024) {
                int r = idx >> 3, v = idx & 7;
                const float* src = hidden + (size_t)(m0 + r) * KDIM + k0 + v * 4;
                CP_ASYNC16(a_dst + (uint32_t)(r * 144 + v * 16), src);
            }
        }
        // B fp16: 1152 x 16B (4 per row of 64B + pad)
        #pragma unroll
        for (int i = 0; i < 3; i++) {
            int idx = tid + i * THREADS;
            int r = idx >> 2, v = idx & 3;
            const __half* src = g_whalf + (size_t)r * KDIM + k0 + v * 8;
            CP_ASYNC16(b_dst + (uint32_t)(r * 80 + v * 16), src);
        }
    };

    issue_stage(0, 0); CP_COMMIT();
    issue_stage(1, 1); CP_COMMIT();

    __half* ah = reinterpret_cast<__half*>(smem + SM_AH);

    for (int kc = 0; kc < NCH; kc++) {
        CP_WAIT(1);            // stage kc complete (kc+1 may be in flight)
        __syncthreads();       // + all warps done with compute kc-1 (Ahalf free)

        const int buf = kc % STAGES;
        // convert raw f32 A[kc] -> fp16 Ahalf (single buffer)
        {
            const float4* raw4 = reinterpret_cast<const float4*>(
                smem + SM_STG + buf * STAGE_SZ);
            #pragma unroll
            for (int i = 0; i < 3; i++) {
                int idx = tid + i * THREADS;
                if (idx < 1024) {
                    int r = idx >> 3, v = idx & 7;
                    float4 f = raw4[r * 9 + v];            // LDA_RAW/4 = 9
                    __half2 h0 = __floats2half2_rn(f.x, f.y);
                    __half2 h1 = __floats2half2_rn(f.z, f.w);
                    __half2* dst = reinterpret_cast<__half2*>(ah + r * LDH + v * 4);
                    dst[0] = h0;
                    dst[1] = h1;
                }
            }
        }
        __syncthreads();       // Ahalf visible to all warps

        const __half* Bs = reinterpret_cast<const __half*>(
            smem + SM_STG + buf * STAGE_SZ + A_RAW_SZ);

        #pragma unroll
        for (int ks = 0; ks < 2; ks++) {
            const int k0 = ks * 16;
            wmma::fragment<wmma::matrix_a, 16, 16, 16, __half,
                           wmma::row_major> a[4];
            wmma::fragment<wmma::matrix_b, 16, 16, 16, __half,
                           wmma::col_major> b[3];
            #pragma unroll
            for (int i = 0; i < 4; i++)
                wmma::load_matrix_sync(a[i], ah + (wm * 64 + i * 16) * LDH + k0, LDH);
            #pragma unroll
            for (int j = 0; j < 3; j++)
                wmma::load_matrix_sync(b[j], Bs + (wn * 48 + j * 16) * LDH + k0, LDH);
            #pragma unroll
            for (int i = 0; i < 4; i++)
                #pragma unroll
                for (int j = 0; j < 3; j++)
                    wmma::mma_sync(c[i][j], a[i], b[j], c[i][j]);
        }

        // R4-proven ordering: prefetch issue AFTER compute
        if (kc + 2 < NCH) issue_stage(kc + 2, (kc + 2) % STAGES);
        CP_COMMIT();           // uniform group count even when empty
    }
    __syncthreads();           // all warps done with stage smem

    // ---- epilogue: full 128x292 C in smem (one pass) ----
    float* Cs = reinterpret_cast<float*>(smem + SM_C);
    #pragma unroll
    for (int i = 0; i < 4; i++)
        #pragma unroll
        for (int j = 0; j < 3; j++)
            wmma::store_matrix_sync(
                Cs + (wm * 64 + i * 16) * LDC + wn * 48 + j * 16,
                c[i][j], LDC, wmma::mem_row_major);
    __syncthreads();

    // logits: float4 LDS (aligned) -> 4 scalar STG (logits base may be 4B-aligned)
    for (int idx = tid; idx < BM * (NTOT / 4); idx += THREADS) {
        int r = idx / (NTOT / 4), n4 = idx - r * (NTOT / 4);
        float4 v  = *reinterpret_cast<const float4*>(Cs + r * LDC + n4 * 4);
        float4 bb = *reinterpret_cast<const float4*>(sbias + n4 * 4);
        float* dst = logits + (size_t)(m0 + r) * NTOT + n4 * 4;
        dst[0] = v.x + bb.x;
        dst[1] = v.y + bb.y;
        dst[2] = v.z + bb.z;
        dst[3] = v.w + bb.w;
    }

    // loss: 128 rows x 28 heads
    const int lab64 = g_lab64;
    float loss_part = 0.f;
    for (int t = tid; t < BM * 28; t += THREADS) {
        int r = t / 28, h = t - r * 28;
        const float* x  = Cs + r * LDC + h * 10;
        const float* bb = sbias + h * 10;
        float v[10], mx = -1e30f;
        #pragma unroll
        for (int i = 0; i < 10; i++) { v[i] = x[i] + bb[i]; mx = fmaxf(mx, v[i]); }
        float s = 0.f;
        #pragma unroll
        for (int i = 0; i < 10; i++) s += __expf(v[i] - mx);
        int li = (m0 + r) * 28 + h;
        int label = lab64 ? lab[2 * li] : lab[li];
        loss_part += mx + __logf(s) - v[label];
    }

    #pragma unroll
    for (int off = 16; off > 0; off >>= 1)
        loss_part += __shfl_xor_sync(0xFFFFFFFF, loss_part, off);
    __shared__ float warp_loss[12];
    if ((tid & 31) == 0) warp_loss[wid] = loss_part;
    __syncthreads();
    if (tid == 0) {
        float t = 0.f;
        #pragma unroll
        for (int i = 0; i < 12; i++) t += warp_loss[i];
        atomicAdd(loss_out, t * (1.0f / ((float)batch * 28.0f)));
    }
}

// ============================================================================
// kernel_launch
// ============================================================================
extern "C" void kernel_launch(void* const* d_in, const int* in_sizes, int n_in,
                              void* d_out, int out_size)
{
    const float* hidden = (const float*)d_in[0];
    const int*   labels = (const int*)d_in[1];
    const float* W      = (const float*)d_in[2];
    const float* bias   = (const float*)d_in[3];

    const int batch = in_sizes[0] / KDIM;                  // 32768
    const long long LOGN = (long long)batch * NTOT;

    float* out = (float*)d_out;
    float* loss_ptr = nullptr;
    float* logits_ptr = nullptr;
    if ((long long)out_size >= LOGN + 1) {
        loss_ptr = out;
        logits_ptr = out + 1;
    } else if ((long long)out_size == LOGN) {
        logits_ptr = out;
    } else {
        loss_ptr = out;
    }
    if (!loss_ptr) {
        void* p = nullptr;
        cudaGetSymbolAddress(&p, g_loss_scratch);
        loss_ptr = (float*)p;
    }

    static bool attr_done = false;
    if (!attr_done) {
        cudaFuncSetAttribute(gemm_loss_kernel,
                             cudaFuncAttributeMaxDynamicSharedMemorySize, SM_TOTAL);
        attr_done = true;
    }

    prep_kernel<<<(NPAD * KDIM + 255) / 256, 256>>>(W, labels);
    cudaMemsetAsync(loss_ptr, 0, sizeof(float));
    gemm_loss_kernel<<<batch / BM, THREADS, SM_TOTAL>>>(
        hidden, bias, labels, logits_ptr, loss_ptr, batch);
}